// round 2
// baseline (speedup 1.0000x reference)
#include <cuda_runtime.h>

#define GS     16
#define NPAIR  136          // 16*17/2 lower-triangular pairs
#define NACC   152          // 136 pair sums + 16 channel sums
#define GROUPS 32
#define BATCH  32
#define HW     3136         // 56*56
#define HW2    1568         // HW/2 (float2 units)
#define CH     512

static __device__ float d_acc[GROUPS][NACC];   // pair sums + channel sums
static __device__ float d_Linv[GROUPS][NPAIR]; // packed lower-triangular Linv
static __device__ float d_bias[CH];            // Linv @ mean, per channel

// ---------------------------------------------------------------------------
__global__ void zero_kernel() {
    int i = blockIdx.x * blockDim.x + threadIdx.x;
    if (i < GROUPS * NACC) ((float*)d_acc)[i] = 0.f;
}

// ---------------------------------------------------------------------------
// Stats v2: warp-specialized pair-block decomposition so registers fit.
//   warps 0-2 : pairs within channels 0-7   (36 pairs + 8 sums), 96 lanes
//   warps 3-5 : pairs within channels 8-15  (36 pairs + 8 sums), 96 lanes
//   warps 6-9 : cross pairs (i in 8-15, j in 0-7), 64 pairs, 128 lanes
// Each role strides over all HW2 float2 positions of its (batch,group) tile.
__global__ void __launch_bounds__(320) stats_kernel(const float* __restrict__ x) {
    const int g = blockIdx.x & 31;
    const int b = blockIdx.x >> 5;
    const float2* in = (const float2*)(x + ((size_t)b * CH + (size_t)g * GS) * HW);

    const int tid  = threadIdx.x;
    const int wid  = tid >> 5;
    const int lane = tid & 31;

    if (wid < 6) {
        // -------- diagonal half-blocks: 36 pairs + 8 sums over 8 channels --
        const int co = (wid < 3) ? 0 : 8;            // channel offset
        const int id = (wid < 3) ? tid : tid - 96;   // 0..95
        float acc[44];
#pragma unroll
        for (int k = 0; k < 44; k++) acc[k] = 0.f;

        for (int pos = id; pos < HW2; pos += 96) {
            float2 v[8];
#pragma unroll
            for (int c = 0; c < 8; c++) v[c] = __ldg(in + (size_t)(co + c) * HW2 + pos);
#pragma unroll
            for (int i = 0; i < 8; i++) {
#pragma unroll
                for (int j = 0; j <= i; j++) {
                    const int k = i * (i + 1) / 2 + j;
                    acc[k] = fmaf(v[i].x, v[j].x, acc[k]);
                    acc[k] = fmaf(v[i].y, v[j].y, acc[k]);
                }
                acc[36 + i] += v[i].x + v[i].y;
            }
        }
#pragma unroll
        for (int k = 0; k < 44; k++) {
#pragma unroll
            for (int off = 16; off > 0; off >>= 1)
                acc[k] += __shfl_xor_sync(0xffffffffu, acc[k], off);
        }
        if (lane == 0) {
            int k = 0;
            for (int i = 0; i < 8; i++)
                for (int j = 0; j <= i; j++) {
                    const int gi = i + co, gj = j + co;
                    atomicAdd(&d_acc[g][gi * (gi + 1) / 2 + gj], acc[k++]);
                }
            for (int i = 0; i < 8; i++)
                atomicAdd(&d_acc[g][NPAIR + co + i], acc[36 + i]);
        }
    } else {
        // -------- cross block: 64 pairs (i in H1, j in H0) ------------------
        const int id = tid - 192;  // 0..127
        float acc[64];
#pragma unroll
        for (int k = 0; k < 64; k++) acc[k] = 0.f;

        for (int pos = id; pos < HW2; pos += 128) {
            float2 u[8], w[8];
#pragma unroll
            for (int c = 0; c < 8; c++) {
                w[c] = __ldg(in + (size_t)c * HW2 + pos);
                u[c] = __ldg(in + (size_t)(8 + c) * HW2 + pos);
            }
#pragma unroll
            for (int i = 0; i < 8; i++)
#pragma unroll
                for (int j = 0; j < 8; j++) {
                    const int k = i * 8 + j;
                    acc[k] = fmaf(u[i].x, w[j].x, acc[k]);
                    acc[k] = fmaf(u[i].y, w[j].y, acc[k]);
                }
        }
#pragma unroll
        for (int k = 0; k < 64; k++) {
#pragma unroll
            for (int off = 16; off > 0; off >>= 1)
                acc[k] += __shfl_xor_sync(0xffffffffu, acc[k], off);
        }
        if (lane == 0) {
            for (int i = 0; i < 8; i++)
                for (int j = 0; j < 8; j++) {
                    const int gi = i + 8;
                    atomicAdd(&d_acc[g][gi * (gi + 1) / 2 + j], acc[i * 8 + j]);
                }
        }
    }
}

// ---------------------------------------------------------------------------
// Per-group 16x16: cov -> shrink -> Cholesky -> inverse of L -> bias. fp64.
__global__ void solve_kernel() {
    const int g = threadIdx.x;
    if (g >= GROUPS) return;
    const double Nd   = (double)BATCH * (double)HW;
    const double EPSd = 1e-3;

    double m[GS];
#pragma unroll
    for (int i = 0; i < GS; i++) m[i] = (double)d_acc[g][NPAIR + i] / Nd;

    double P[GS][GS];
    for (int i = 0; i < GS; i++)
        for (int j = 0; j <= i; j++) {
            double c = (double)d_acc[g][i * (i + 1) / 2 + j] / Nd - m[i] * m[j];
            c *= (1.0 - EPSd);
            if (i == j) c += EPSd;
            P[i][j] = c;
        }

    double L[GS][GS];
    for (int j = 0; j < GS; j++) {
        double s = P[j][j];
        for (int k = 0; k < j; k++) s -= L[j][k] * L[j][k];
        double ljj = sqrt(s);
        L[j][j] = ljj;
        for (int i = j + 1; i < GS; i++) {
            double t = P[i][j];
            for (int k = 0; k < j; k++) t -= L[i][k] * L[j][k];
            L[i][j] = t / ljj;
        }
    }

    double inv[GS][GS];
    for (int j = 0; j < GS; j++) {
        inv[j][j] = 1.0 / L[j][j];
        for (int i = j + 1; i < GS; i++) {
            double t = 0.0;
            for (int k = j; k < i; k++) t += L[i][k] * inv[k][j];
            inv[i][j] = -t / L[i][i];
        }
    }

    for (int i = 0; i < GS; i++) {
        double bsum = 0.0;
        for (int j = 0; j <= i; j++) {
            d_Linv[g][i * (i + 1) / 2 + j] = (float)inv[i][j];
            bsum += inv[i][j] * m[j];
        }
        d_bias[g * GS + i] = (float)bsum;
    }
}

// ---------------------------------------------------------------------------
// Apply: out_i = sum_{j<=i} Linv_ij * x_j - bias_i. float2, reg-capped so
// occupancy reaches >=2 blocks/SM. Two blocks per (b,g) tile.
__global__ void __launch_bounds__(256, 2) apply_kernel(const float* __restrict__ x,
                                                       float* __restrict__ out) {
    const int bg   = blockIdx.x >> 1;
    const int half = blockIdx.x & 1;
    const int g = bg & 31;
    const int b = bg >> 5;

    __shared__ float Ls[NPAIR];
    __shared__ float bs[GS];
    if (threadIdx.x < NPAIR) Ls[threadIdx.x] = d_Linv[g][threadIdx.x];
    if (threadIdx.x < GS)    bs[threadIdx.x] = d_bias[g * GS + threadIdx.x];
    __syncthreads();

    const size_t off = ((size_t)b * CH + (size_t)g * GS) * HW;
    const float2* in = (const float2*)(x + off);
    float2*       op = (float2*)(out + off);

    const int beg = half * (HW2 / 2);
    const int end = beg + (HW2 / 2);

    for (int pos = beg + threadIdx.x; pos < end; pos += 256) {
        float2 v[GS];
#pragma unroll
        for (int c = 0; c < GS; c++) v[c] = in[(size_t)c * HW2 + pos];
#pragma unroll
        for (int i = 0; i < GS; i++) {
            float ax = -bs[i], ay = -bs[i];
#pragma unroll
            for (int j = 0; j <= i; j++) {
                const float f = Ls[i * (i + 1) / 2 + j];
                ax = fmaf(f, v[j].x, ax);
                ay = fmaf(f, v[j].y, ay);
            }
            float2 r; r.x = ax; r.y = ay;
            op[(size_t)i * HW2 + pos] = r;
        }
    }
}

// ---------------------------------------------------------------------------
extern "C" void kernel_launch(void* const* d_in, const int* in_sizes, int n_in,
                              void* d_out, int out_size) {
    const float* x   = (const float*)d_in[0];
    float*       out = (float*)d_out;

    zero_kernel<<<(GROUPS * NACC + 255) / 256, 256>>>();
    stats_kernel<<<GROUPS * BATCH, 320>>>(x);
    solve_kernel<<<1, 32>>>();
    apply_kernel<<<GROUPS * BATCH * 2, 256>>>(x, out);
}

// round 3
// speedup vs baseline: 2.1577x; 2.1577x over previous
#include <cuda_runtime.h>

#define GS     16
#define NPAIR  136          // 16*17/2 lower-triangular pairs
#define NACC   152          // 136 pair sums + 16 channel sums
#define GROUPS 32
#define BATCH  32
#define HW     3136         // 56*56
#define HW2    1568         // HW/2 (float2 units)
#define HW4    784          // HW/4 (float4 units)
#define CH     512

static __device__ float d_acc[GROUPS][NACC];   // pair sums + channel sums
static __device__ float d_Linv[GROUPS][NPAIR]; // packed lower-triangular Linv
static __device__ float d_bias[CH];            // Linv @ mean, per channel

// ---------------------------------------------------------------------------
__global__ void zero_kernel() {
    int i = blockIdx.x * blockDim.x + threadIdx.x;
    if (i < GROUPS * NACC) ((float*)d_acc)[i] = 0.f;
}

// ---------------------------------------------------------------------------
// Stats: warp-specialized pair-block decomposition so registers fit.
//   warps 0-2 : pairs within channels 0-7   (36 pairs + 8 sums), 96 lanes
//   warps 3-5 : pairs within channels 8-15  (36 pairs + 8 sums), 96 lanes
//   warps 6-9 : cross pairs (i in 8-15, j in 0-7), 64 pairs, 128 lanes
__global__ void __launch_bounds__(320) stats_kernel(const float* __restrict__ x) {
    const int g = blockIdx.x & 31;
    const int b = blockIdx.x >> 5;
    const float2* in = (const float2*)(x + ((size_t)b * CH + (size_t)g * GS) * HW);

    const int tid  = threadIdx.x;
    const int wid  = tid >> 5;
    const int lane = tid & 31;

    if (wid < 6) {
        const int co = (wid < 3) ? 0 : 8;
        const int id = (wid < 3) ? tid : tid - 96;   // 0..95
        float acc[44];
#pragma unroll
        for (int k = 0; k < 44; k++) acc[k] = 0.f;

        for (int pos = id; pos < HW2; pos += 96) {
            float2 v[8];
#pragma unroll
            for (int c = 0; c < 8; c++) v[c] = __ldg(in + (size_t)(co + c) * HW2 + pos);
#pragma unroll
            for (int i = 0; i < 8; i++) {
#pragma unroll
                for (int j = 0; j <= i; j++) {
                    const int k = i * (i + 1) / 2 + j;
                    acc[k] = fmaf(v[i].x, v[j].x, acc[k]);
                    acc[k] = fmaf(v[i].y, v[j].y, acc[k]);
                }
                acc[36 + i] += v[i].x + v[i].y;
            }
        }
#pragma unroll
        for (int k = 0; k < 44; k++) {
#pragma unroll
            for (int off = 16; off > 0; off >>= 1)
                acc[k] += __shfl_xor_sync(0xffffffffu, acc[k], off);
        }
        if (lane == 0) {
            int k = 0;
            for (int i = 0; i < 8; i++)
                for (int j = 0; j <= i; j++) {
                    const int gi = i + co, gj = j + co;
                    atomicAdd(&d_acc[g][gi * (gi + 1) / 2 + gj], acc[k++]);
                }
            for (int i = 0; i < 8; i++)
                atomicAdd(&d_acc[g][NPAIR + co + i], acc[36 + i]);
        }
    } else {
        const int id = tid - 192;  // 0..127
        float acc[64];
#pragma unroll
        for (int k = 0; k < 64; k++) acc[k] = 0.f;

        for (int pos = id; pos < HW2; pos += 128) {
            float2 u[8], w[8];
#pragma unroll
            for (int c = 0; c < 8; c++) {
                w[c] = __ldg(in + (size_t)c * HW2 + pos);
                u[c] = __ldg(in + (size_t)(8 + c) * HW2 + pos);
            }
#pragma unroll
            for (int i = 0; i < 8; i++)
#pragma unroll
                for (int j = 0; j < 8; j++) {
                    const int k = i * 8 + j;
                    acc[k] = fmaf(u[i].x, w[j].x, acc[k]);
                    acc[k] = fmaf(u[i].y, w[j].y, acc[k]);
                }
        }
#pragma unroll
        for (int k = 0; k < 64; k++) {
#pragma unroll
            for (int off = 16; off > 0; off >>= 1)
                acc[k] += __shfl_xor_sync(0xffffffffu, acc[k], off);
        }
        if (lane == 0) {
            for (int i = 0; i < 8; i++)
                for (int j = 0; j < 8; j++) {
                    const int gi = i + 8;
                    atomicAdd(&d_acc[g][gi * (gi + 1) / 2 + j], acc[i * 8 + j]);
                }
        }
    }
}

// ---------------------------------------------------------------------------
// Solve v2: one block per group, 16 threads, all matrices in SHARED memory
// (v1 held 768 doubles/thread in local memory -> serialized LDL/STL disaster).
// Column-parallel Cholesky + per-column triangular inverse, fp64 in smem.
__global__ void __launch_bounds__(16) solve_kernel() {
    const int g = blockIdx.x;
    const int t = threadIdx.x;              // 0..15, one row/column per thread
    __shared__ double P[GS][GS + 1];
    __shared__ double L[GS][GS + 1];
    __shared__ double V[GS][GS + 1];        // inv(L)
    __shared__ double m[GS];

    const double Nd   = (double)BATCH * (double)HW;
    const double EPSd = 1e-3;
    const unsigned MASK = 0xffffu;

    m[t] = (double)d_acc[g][NPAIR + t] / Nd;
    __syncwarp(MASK);

    // row t of shrunk covariance (full symmetric)
    for (int j = 0; j < GS; j++) {
        const int i_ = t > j ? t : j, j_ = t > j ? j : t;
        double c = (double)d_acc[g][i_ * (i_ + 1) / 2 + j_] / Nd - m[t] * m[j];
        c *= (1.0 - EPSd);
        if (t == j) c += EPSd;
        P[t][j] = c;
    }
    __syncwarp(MASK);

    // Cholesky, column by column
    for (int j = 0; j < GS; j++) {
        if (t == j) {
            double s = P[j][j];
            for (int k = 0; k < j; k++) s -= L[j][k] * L[j][k];
            L[j][j] = sqrt(s);
        }
        __syncwarp(MASK);
        if (t > j) {
            double s = P[t][j];
            for (int k = 0; k < j; k++) s -= L[t][k] * L[j][k];
            L[t][j] = s / L[j][j];
        }
        __syncwarp(MASK);
    }

    // inverse of L: thread t computes column t (forward substitution)
    V[t][t] = 1.0 / L[t][t];
    for (int i = t + 1; i < GS; i++) {
        double s = 0.0;
        for (int k = t; k < i; k++) s += L[i][k] * V[k][t];
        V[i][t] = -s / L[i][i];
    }
    __syncwarp(MASK);

    // emit row t of Linv (packed) and bias
    double bsum = 0.0;
    for (int j = 0; j <= t; j++) {
        d_Linv[g][t * (t + 1) / 2 + j] = (float)V[t][j];
        bsum += V[t][j] * m[j];
    }
    d_bias[g * GS + t] = (float)bsum;
}

// ---------------------------------------------------------------------------
// Apply: out_i = sum_{j<=i} Linv_ij * x_j - bias_i. float4 (LDG.128, MLP=16),
// reg-capped to 128 for 2 blocks/SM. Streaming stores (output never re-read).
__global__ void __launch_bounds__(256, 2) apply_kernel(const float* __restrict__ x,
                                                       float* __restrict__ out) {
    const int g = blockIdx.x & 31;
    const int b = blockIdx.x >> 5;

    __shared__ float Ls[NPAIR];
    __shared__ float bs[GS];
    if (threadIdx.x < NPAIR) Ls[threadIdx.x] = d_Linv[g][threadIdx.x];
    if (threadIdx.x < GS)    bs[threadIdx.x] = d_bias[g * GS + threadIdx.x];
    __syncthreads();

    const size_t off = ((size_t)b * CH + (size_t)g * GS) * HW;
    const float4* in = (const float4*)(x + off);
    float4*       op = (float4*)(out + off);

    for (int pos = threadIdx.x; pos < HW4; pos += 256) {
        float4 v[GS];
#pragma unroll
        for (int c = 0; c < GS; c++) v[c] = in[(size_t)c * HW4 + pos];
#pragma unroll
        for (int i = 0; i < GS; i++) {
            const float bias = bs[i];
            float4 a;
            a.x = -bias; a.y = -bias; a.z = -bias; a.w = -bias;
#pragma unroll
            for (int j = 0; j <= i; j++) {
                const float f = Ls[i * (i + 1) / 2 + j];
                a.x = fmaf(f, v[j].x, a.x);
                a.y = fmaf(f, v[j].y, a.y);
                a.z = fmaf(f, v[j].z, a.z);
                a.w = fmaf(f, v[j].w, a.w);
            }
            __stcs(&op[(size_t)i * HW4 + pos], a);
        }
    }
}

// ---------------------------------------------------------------------------
extern "C" void kernel_launch(void* const* d_in, const int* in_sizes, int n_in,
                              void* d_out, int out_size) {
    const float* x   = (const float*)d_in[0];
    float*       out = (float*)d_out;

    zero_kernel<<<(GROUPS * NACC + 255) / 256, 256>>>();
    stats_kernel<<<GROUPS * BATCH, 320>>>(x);
    solve_kernel<<<GROUPS, 16>>>();
    apply_kernel<<<GROUPS * BATCH, 256>>>(x, out);
}

// round 5
// speedup vs baseline: 2.4867x; 1.1525x over previous
#include <cuda_runtime.h>

#define GS     16
#define NPAIR  136          // 16*17/2 lower-triangular pairs
#define NACC   152          // 136 pair sums + 16 channel sums
#define GROUPS 32
#define BATCH  32
#define HW     3136         // 56*56
#define HW4    784          // HW/4 (float4 units)
#define CH     512

typedef unsigned long long ull;

static __device__ float d_acc[GROUPS][NACC];   // pair sums + channel sums
static __device__ float d_Linv[GROUPS][NPAIR]; // packed lower-triangular Linv
static __device__ float d_bias[CH];            // Linv @ mean, per channel

// ---- packed f32x2 helpers (Blackwell) --------------------------------------
__device__ __forceinline__ void fma2(ull& d, ull a, ull b) {
    asm("fma.rn.f32x2 %0, %1, %2, %0;" : "+l"(d) : "l"(a), "l"(b));
}
__device__ __forceinline__ void add2(ull& d, ull a) {
    asm("add.rn.f32x2 %0, %0, %1;" : "+l"(d) : "l"(a));
}
__device__ __forceinline__ float unpack_add(ull v) {
    float lo, hi;
    asm("mov.b64 {%0,%1}, %2;" : "=f"(lo), "=f"(hi) : "l"(v));
    return lo + hi;
}
__device__ __forceinline__ ull pack2(float lo, float hi) {
    ull r;
    asm("mov.b64 %0, {%1,%2};" : "=l"(r) : "f"(lo), "f"(hi));
    return r;
}

struct V2 { ull a, b; };   // one float4 = two packed f32x2 halves

__device__ __forceinline__ V2 ld_v2(const float4* p) {
    const float4 f = __ldg(p);
    V2 v;
    v.a = pack2(f.x, f.y);
    v.b = pack2(f.z, f.w);
    return v;
}

// ---------------------------------------------------------------------------
__global__ void zero_kernel() {
    int i = blockIdx.x * blockDim.x + threadIdx.x;
    if (i < GROUPS * NACC) ((float*)d_acc)[i] = 0.f;
}

// ---------------------------------------------------------------------------
// Stats v3: float4 loads + fma.rn.f32x2 packed accumulation.
// 12 warps, 4 roles of 3 warps (96 lanes each), one block per (batch,group):
//   role 0: diag pairs in ch0-7   (36 packed acc + 8 packed sums)
//   role 1: diag pairs in ch8-15
//   role 2: cross i in 8-15, j in 0-3  (32 packed acc)
//   role 3: cross i in 8-15, j in 4-7
__global__ void __launch_bounds__(384) stats_kernel(const float* __restrict__ x) {
    const int g = blockIdx.x & 31;
    const int b = blockIdx.x >> 5;
    const float4* in = (const float4*)(x + ((size_t)b * CH + (size_t)g * GS) * HW);

    const int tid  = threadIdx.x;
    const int wid  = tid >> 5;
    const int lane = tid & 31;
    const int role = wid / 3;              // 0..3
    const int id   = tid - role * 96;      // 0..95 within role

    if (role < 2) {
        // ---------------- diagonal roles ------------------------------------
        const int co = role * 8;
        ull acc[36], sum[8];
#pragma unroll
        for (int k = 0; k < 36; k++) acc[k] = 0ull;
#pragma unroll
        for (int k = 0; k < 8; k++) sum[k] = 0ull;

        for (int pos = id; pos < HW4; pos += 96) {
            V2 v[8];
#pragma unroll
            for (int c = 0; c < 8; c++) v[c] = ld_v2(in + (size_t)(co + c) * HW4 + pos);
#pragma unroll
            for (int i = 0; i < 8; i++) {
#pragma unroll
                for (int j = 0; j <= i; j++) {
                    const int k = i * (i + 1) / 2 + j;
                    fma2(acc[k], v[i].a, v[j].a);
                    fma2(acc[k], v[i].b, v[j].b);
                }
                add2(sum[i], v[i].a);
                add2(sum[i], v[i].b);
            }
        }

        float r[44];
#pragma unroll
        for (int k = 0; k < 36; k++) r[k] = unpack_add(acc[k]);
#pragma unroll
        for (int k = 0; k < 8; k++)  r[36 + k] = unpack_add(sum[k]);
#pragma unroll
        for (int k = 0; k < 44; k++) {
#pragma unroll
            for (int off = 16; off > 0; off >>= 1)
                r[k] += __shfl_xor_sync(0xffffffffu, r[k], off);
        }
        if (lane == 0) {
            int k = 0;
            for (int i = 0; i < 8; i++)
                for (int j = 0; j <= i; j++) {
                    const int gi = i + co, gj = j + co;
                    atomicAdd(&d_acc[g][gi * (gi + 1) / 2 + gj], r[k++]);
                }
            for (int i = 0; i < 8; i++)
                atomicAdd(&d_acc[g][NPAIR + co + i], r[36 + i]);
        }
    } else {
        // ---------------- cross roles: i in 8-15, j in jo..jo+3 -------------
        const int jo = (role - 2) * 4;
        ull acc[32];
#pragma unroll
        for (int k = 0; k < 32; k++) acc[k] = 0ull;

        for (int pos = id; pos < HW4; pos += 96) {
            V2 u[8], w[4];
#pragma unroll
            for (int c = 0; c < 8; c++) u[c] = ld_v2(in + (size_t)(8 + c) * HW4 + pos);
#pragma unroll
            for (int c = 0; c < 4; c++) w[c] = ld_v2(in + (size_t)(jo + c) * HW4 + pos);
#pragma unroll
            for (int i = 0; i < 8; i++)
#pragma unroll
                for (int j = 0; j < 4; j++) {
                    const int k = i * 4 + j;
                    fma2(acc[k], u[i].a, w[j].a);
                    fma2(acc[k], u[i].b, w[j].b);
                }
        }

        float r[32];
#pragma unroll
        for (int k = 0; k < 32; k++) r[k] = unpack_add(acc[k]);
#pragma unroll
        for (int k = 0; k < 32; k++) {
#pragma unroll
            for (int off = 16; off > 0; off >>= 1)
                r[k] += __shfl_xor_sync(0xffffffffu, r[k], off);
        }
        if (lane == 0) {
            for (int i = 0; i < 8; i++)
                for (int j = 0; j < 4; j++) {
                    const int gi = 8 + i, gj = jo + j;
                    atomicAdd(&d_acc[g][gi * (gi + 1) / 2 + gj], r[i * 4 + j]);
                }
        }
    }
}

// ---------------------------------------------------------------------------
// Solve: one block per group, 16 threads, everything in shared memory, fp64.
__global__ void __launch_bounds__(16) solve_kernel() {
    const int g = blockIdx.x;
    const int t = threadIdx.x;
    __shared__ double P[GS][GS + 1];
    __shared__ double L[GS][GS + 1];
    __shared__ double V[GS][GS + 1];
    __shared__ double m[GS];

    const double Nd   = (double)BATCH * (double)HW;
    const double EPSd = 1e-3;
    const unsigned MASK = 0xffffu;

    m[t] = (double)d_acc[g][NPAIR + t] / Nd;
    __syncwarp(MASK);

    for (int j = 0; j < GS; j++) {
        const int i_ = t > j ? t : j, j_ = t > j ? j : t;
        double c = (double)d_acc[g][i_ * (i_ + 1) / 2 + j_] / Nd - m[t] * m[j];
        c *= (1.0 - EPSd);
        if (t == j) c += EPSd;
        P[t][j] = c;
    }
    __syncwarp(MASK);

    for (int j = 0; j < GS; j++) {
        if (t == j) {
            double s = P[j][j];
            for (int k = 0; k < j; k++) s -= L[j][k] * L[j][k];
            L[j][j] = sqrt(s);
        }
        __syncwarp(MASK);
        if (t > j) {
            double s = P[t][j];
            for (int k = 0; k < j; k++) s -= L[t][k] * L[j][k];
            L[t][j] = s / L[j][j];
        }
        __syncwarp(MASK);
    }

    V[t][t] = 1.0 / L[t][t];
    for (int i = t + 1; i < GS; i++) {
        double s = 0.0;
        for (int k = t; k < i; k++) s += L[i][k] * V[k][t];
        V[i][t] = -s / L[i][i];
    }
    __syncwarp(MASK);

    double bsum = 0.0;
    for (int j = 0; j <= t; j++) {
        d_Linv[g][t * (t + 1) / 2 + j] = (float)V[t][j];
        bsum += V[t][j] * m[j];
    }
    d_bias[g * GS + t] = (float)bsum;
}

// ---------------------------------------------------------------------------
// Apply (unchanged from R3, proven 65.6us / 68.7% DRAM):
// out_i = sum_{j<=i} Linv_ij * x_j - bias_i, float4, streaming stores.
__global__ void __launch_bounds__(256, 2) apply_kernel(const float* __restrict__ x,
                                                       float* __restrict__ out) {
    const int g = blockIdx.x & 31;
    const int b = blockIdx.x >> 5;

    __shared__ float Ls[NPAIR];
    __shared__ float bs[GS];
    if (threadIdx.x < NPAIR) Ls[threadIdx.x] = d_Linv[g][threadIdx.x];
    if (threadIdx.x < GS)    bs[threadIdx.x] = d_bias[g * GS + threadIdx.x];
    __syncthreads();

    const size_t off = ((size_t)b * CH + (size_t)g * GS) * HW;
    const float4* in = (const float4*)(x + off);
    float4*       op = (float4*)(out + off);

    for (int pos = threadIdx.x; pos < HW4; pos += 256) {
        float4 v[GS];
#pragma unroll
        for (int c = 0; c < GS; c++) v[c] = in[(size_t)c * HW4 + pos];
#pragma unroll
        for (int i = 0; i < GS; i++) {
            const float bias = bs[i];
            float4 a;
            a.x = -bias; a.y = -bias; a.z = -bias; a.w = -bias;
#pragma unroll
            for (int j = 0; j <= i; j++) {
                const float f = Ls[i * (i + 1) / 2 + j];
                a.x = fmaf(f, v[j].x, a.x);
                a.y = fmaf(f, v[j].y, a.y);
                a.z = fmaf(f, v[j].z, a.z);
                a.w = fmaf(f, v[j].w, a.w);
            }
            __stcs(&op[(size_t)i * HW4 + pos], a);
        }
    }
}

// ---------------------------------------------------------------------------
extern "C" void kernel_launch(void* const* d_in, const int* in_sizes, int n_in,
                              void* d_out, int out_size) {
    const float* x   = (const float*)d_in[0];
    float*       out = (float*)d_out;

    zero_kernel<<<(GROUPS * NACC + 255) / 256, 256>>>();
    stats_kernel<<<GROUPS * BATCH, 384>>>(x);
    solve_kernel<<<GROUPS, 16>>>();
    apply_kernel<<<GROUPS * BATCH, 256>>>(x, out);
}